// round 6
// baseline (speedup 1.0000x reference)
#include <cuda_runtime.h>
#include <math.h>

#define BB 64
#define TT 500
#define SS 50
#define DD 64
#define NTOK (BB*TT)

__device__ float g_w[(size_t)NTOK*SS];
__device__ float g_e[(size_t)NTOK*DD];
__device__ float g_a[(size_t)NTOK*DD];
__device__ float g_r[(size_t)NTOK*DD];

__device__ __forceinline__ float fast_sigmoid(float x) {
    return 1.f / (1.f + __expf(-x));
}
__device__ __forceinline__ float fast_tanh(float x) {
    return fmaf(2.f, fast_sigmoid(2.f * x), -1.f);
}

// ============================================================
// k_scores: w = softmax_s(k @ Mk^T). 64 tok/block, 128 thr, grid 500.
// (unchanged from 140us round)
// ============================================================
#define SROW 52
__global__ __launch_bounds__(128) void k_scores(const int* __restrict__ concept,
                                                const float* __restrict__ ek,
                                                const float* __restrict__ Mk) {
    __shared__ __align__(16) float sMkT[64 * SROW + 16];
    __shared__ __align__(16) float sx[64 * 64];
    __shared__ int sc_[64];

    int tid = threadIdx.x;
    int base = blockIdx.x * 64;
    int td = tid & 15, tt = tid >> 4;

    for (int q = tid; q < 64 * SROW + 16; q += 128) sMkT[q] = 0.f;
    if (tid < 64) sc_[tid] = concept[base + tid];
    __syncthreads();
    for (int q = tid; q < SS * DD; q += 128) {
        int s = q >> 6, k = q & 63;
        sMkT[k * SROW + s] = Mk[q];
    }
    __syncthreads();

    float4* sx4 = (float4*)sx;
    const float4* ek4 = (const float4*)ek;
    for (int q = tid; q < 1024; q += 128) {
        int tok = q >> 4, kk = q & 15;
        sx4[q] = ek4[(size_t)sc_[tok] * 16 + kk];
    }
    __syncthreads();

    const float4* sM4 = (const float4*)sMkT;
    float acc[8][4];
#pragma unroll
    for (int j = 0; j < 8; ++j)
#pragma unroll
        for (int ss = 0; ss < 4; ++ss) acc[j][ss] = 0.f;

#pragma unroll
    for (int kk = 0; kk < 16; ++kk) {
        float4 w0 = sM4[(4 * kk + 0) * 13 + td];
        float4 w1 = sM4[(4 * kk + 1) * 13 + td];
        float4 w2 = sM4[(4 * kk + 2) * 13 + td];
        float4 w3 = sM4[(4 * kk + 3) * 13 + td];
#pragma unroll
        for (int j = 0; j < 8; ++j) {
            float4 xv = sx4[(tt + 8 * j) * 16 + kk];
            acc[j][0] += xv.x * w0.x + xv.y * w1.x + xv.z * w2.x + xv.w * w3.x;
            acc[j][1] += xv.x * w0.y + xv.y * w1.y + xv.z * w2.y + xv.w * w3.y;
            acc[j][2] += xv.x * w0.z + xv.y * w1.z + xv.z * w2.z + xv.w * w3.z;
            acc[j][3] += xv.x * w0.w + xv.y * w1.w + xv.z * w2.w + xv.w * w3.w;
        }
    }

#pragma unroll
    for (int j = 0; j < 8; ++j) {
        float p = 0.f;
#pragma unroll
        for (int ss = 0; ss < 4; ++ss) {
            bool ok = (4 * td + ss) < SS;
            float e = ok ? __expf(acc[j][ss]) : 0.f;
            acc[j][ss] = e;
            p += e;
        }
        p += __shfl_xor_sync(0xffffffffu, p, 1);
        p += __shfl_xor_sync(0xffffffffu, p, 2);
        p += __shfl_xor_sync(0xffffffffu, p, 4);
        p += __shfl_xor_sync(0xffffffffu, p, 8);
        float inv = 1.f / p;
        int tok = base + tt + 8 * j;
        float* gwp = g_w + (size_t)tok * SS + 4 * td;
        if (td < 12) {
            *(float2*)gwp       = make_float2(acc[j][0] * inv, acc[j][1] * inv);
            *(float2*)(gwp + 2) = make_float2(acc[j][2] * inv, acc[j][3] * inv);
        } else if (td == 12) {
            *(float2*)gwp       = make_float2(acc[j][0] * inv, acc[j][1] * inv);
        }
    }
}

// ============================================================
// k_ea: 64 tok/block, 256 thr, grid 500. Dynamic smem 48KB.
// (unchanged from 140us round)
// ============================================================
extern __shared__ float dynsh[];
__global__ __launch_bounds__(256) void k_ea(const int* __restrict__ concept,
                                            const int* __restrict__ correct,
                                            const int* __restrict__ nc_ptr,
                                            const float* __restrict__ ev,
                                            const float* __restrict__ We,
                                            const float* __restrict__ be,
                                            const float* __restrict__ Wa,
                                            const float* __restrict__ ba) {
    float* sWe = dynsh;
    float* sWa = dynsh + 4096;
    float* sx  = dynsh + 8192;
    __shared__ int sidx[64];

    int tid = threadIdx.x;
    int base = blockIdx.x * 64;
    int td = tid & 15, tt = tid >> 4;
    int nc = *nc_ptr;

    float4* sWe4w = (float4*)sWe;
    float4* sWa4w = (float4*)sWa;
    const float4* We4 = (const float4*)We;
    const float4* Wa4 = (const float4*)Wa;
    for (int q = tid; q < 1024; q += 256) {
        sWe4w[q] = We4[q];
        sWa4w[q] = Wa4[q];
    }
    if (tid < 64) sidx[tid] = concept[base + tid] + nc * correct[base + tid];
    __syncthreads();

    float4* sx4 = (float4*)sx;
    const float4* ev4 = (const float4*)ev;
    for (int q = tid; q < 1024; q += 256) {
        int tok = q >> 4, kk = q & 15;
        sx4[q] = ev4[(size_t)sidx[tok] * 16 + kk];
    }
    __syncthreads();

    const float4* sWe4 = (const float4*)sWe;
    const float4* sWa4 = (const float4*)sWa;
    float ae[4][4], aa[4][4];
#pragma unroll
    for (int j = 0; j < 4; ++j)
#pragma unroll
        for (int dd = 0; dd < 4; ++dd) { ae[j][dd] = 0.f; aa[j][dd] = 0.f; }

#pragma unroll
    for (int kk = 0; kk < 16; ++kk) {
        float4 e0 = sWe4[(4 * kk + 0) * 16 + td];
        float4 e1 = sWe4[(4 * kk + 1) * 16 + td];
        float4 e2 = sWe4[(4 * kk + 2) * 16 + td];
        float4 e3 = sWe4[(4 * kk + 3) * 16 + td];
        float4 a0 = sWa4[(4 * kk + 0) * 16 + td];
        float4 a1 = sWa4[(4 * kk + 1) * 16 + td];
        float4 a2 = sWa4[(4 * kk + 2) * 16 + td];
        float4 a3 = sWa4[(4 * kk + 3) * 16 + td];
#pragma unroll
        for (int j = 0; j < 4; ++j) {
            float4 xv = sx4[(tt + 16 * j) * 16 + kk];
            ae[j][0] += xv.x * e0.x + xv.y * e1.x + xv.z * e2.x + xv.w * e3.x;
            ae[j][1] += xv.x * e0.y + xv.y * e1.y + xv.z * e2.y + xv.w * e3.y;
            ae[j][2] += xv.x * e0.z + xv.y * e1.z + xv.z * e2.z + xv.w * e3.z;
            ae[j][3] += xv.x * e0.w + xv.y * e1.w + xv.z * e2.w + xv.w * e3.w;
            aa[j][0] += xv.x * a0.x + xv.y * a1.x + xv.z * a2.x + xv.w * a3.x;
            aa[j][1] += xv.x * a0.y + xv.y * a1.y + xv.z * a2.y + xv.w * a3.y;
            aa[j][2] += xv.x * a0.z + xv.y * a1.z + xv.z * a2.z + xv.w * a3.z;
            aa[j][3] += xv.x * a0.w + xv.y * a1.w + xv.z * a2.w + xv.w * a3.w;
        }
    }

    float4 bev = *(const float4*)(be + 4 * td);
    float4 bav = *(const float4*)(ba + 4 * td);
#pragma unroll
    for (int j = 0; j < 4; ++j) {
        size_t tok = (size_t)(base + tt + 16 * j);
        float4 eo, ao;
        eo.x = fast_sigmoid(ae[j][0] + bev.x);
        eo.y = fast_sigmoid(ae[j][1] + bev.y);
        eo.z = fast_sigmoid(ae[j][2] + bev.z);
        eo.w = fast_sigmoid(ae[j][3] + bev.w);
        ao.x = fast_tanh(aa[j][0] + bav.x);
        ao.y = fast_tanh(aa[j][1] + bav.y);
        ao.z = fast_tanh(aa[j][2] + bav.z);
        ao.w = fast_tanh(aa[j][3] + bav.w);
        *(float4*)(g_e + tok * DD + 4 * td) = eo;
        *(float4*)(g_a + tok * DD + 4 * td) = ao;
    }
}

// ============================================================
// k_scan: 128 blocks = (b, d-half), 256 thr -> ONE wave on 148 SMs.
// dl = tid>>3 (32 dims), h = tid&7 (7 s-states each, pad 50->56).
// Chunked double-buffered staging, CH=10.
// ============================================================
#define CH 10
__global__ __launch_bounds__(256) void k_scan(const float* __restrict__ Mv0) {
    int b = blockIdx.x >> 1, half = blockIdx.x & 1;
    int tid = threadIdx.x;
    int dl = tid >> 3, h = tid & 7;
    int d = half * 32 + dl;
    int sbase = h * 7;

    __shared__ __align__(16) float sw[2][CH][56];
    __shared__ __align__(16) float se[2][CH][32];
    __shared__ __align__(16) float sa[2][CH][32];
    __shared__ __align__(16) float srb[CH][32];

    for (int q = tid; q < 2 * CH * 6; q += 256) {
        int bf = q / (CH * 6), rem = q % (CH * 6), t = rem / 6, p = rem % 6;
        sw[bf][t][50 + p] = 0.f;
    }

    float mv[7];
#pragma unroll
    for (int i = 0; i < 7; i++) {
        int s = sbase + i;
        mv[i] = (s < SS) ? Mv0[s * DD + d] : 0.f;
    }

    const float* gw = g_w + (size_t)b * TT * SS;
    const float* ge = g_e + (size_t)b * TT * DD + half * 32;
    const float* ga = g_a + (size_t)b * TT * DD + half * 32;
    float* gr = g_r + (size_t)b * TT * DD + half * 32;

    // staging roles
    bool do_w = tid < 250;                 int wt = tid / 25, wp = tid % 25;
    bool do_e = tid < 80;                  int et = tid >> 3, ep = tid & 7;
    bool do_a = (tid >= 80 && tid < 160);  int at = (tid - 80) >> 3, ap = (tid - 80) & 7;

    float2 wreg;
    float4 eareg;

    if (do_w) wreg = *(const float2*)(gw + (size_t)wt * SS + 2 * wp);
    if (do_e) eareg = *(const float4*)(ge + (size_t)et * DD + 4 * ep);
    else if (do_a) eareg = *(const float4*)(ga + (size_t)at * DD + 4 * ap);

    if (do_w) *(float2*)&sw[0][wt][2 * wp] = wreg;
    if (do_e) *(float4*)&se[0][et][4 * ep] = eareg;
    else if (do_a) *(float4*)&sa[0][at][4 * ap] = eareg;
    __syncthreads();

    for (int c = 0; c < TT / CH; ++c) {
        int cur = c & 1;
        if (c < TT / CH - 1) {
            int t0 = (c + 1) * CH;
            if (do_w) wreg = *(const float2*)(gw + (size_t)(t0 + wt) * SS + 2 * wp);
            if (do_e) eareg = *(const float4*)(ge + (size_t)(t0 + et) * DD + 4 * ep);
            else if (do_a) eareg = *(const float4*)(ga + (size_t)(t0 + at) * DD + 4 * ap);
        }

#pragma unroll
        for (int tl = 0; tl < CH; ++tl) {
            float e_d = se[cur][tl][dl], a_d = sa[cur][tl][dl];
            float r = 0.f;
#pragma unroll
            for (int i = 0; i < 7; i++) {
                float ws = sw[cur][tl][sbase + i];
                r += ws * mv[i];
                mv[i] = fmaf(ws, fmaf(-mv[i], e_d, a_d), mv[i]);
            }
            r += __shfl_xor_sync(0xffffffffu, r, 1);
            r += __shfl_xor_sync(0xffffffffu, r, 2);
            r += __shfl_xor_sync(0xffffffffu, r, 4);
            if (h == 0) srb[tl][dl] = r;
        }
        __syncthreads();

        {
            int t0 = c * CH;
            if (tid < 80) {
                int t = tid >> 3, p = tid & 7;
                *(float4*)(gr + (size_t)(t0 + t) * DD + 4 * p) = *(const float4*)&srb[t][4 * p];
            }
        }
        if (c < TT / CH - 1) {
            int nb = cur ^ 1;
            if (do_w) *(float2*)&sw[nb][wt][2 * wp] = wreg;
            if (do_e) *(float4*)&se[nb][et][4 * ep] = eareg;
            else if (do_a) *(float4*)&sa[nb][at][4 * ap] = eareg;
        }
        __syncthreads();
    }
}

// ============================================================
// k_out: 64 tok/block, 256 thr, grid 500. Dynamic smem 64KB:
// sWf 32KB | sx 32KB. 4 tok x 4 dims per thread -> 3 blocks/SM.
// ============================================================
__global__ __launch_bounds__(256) void k_out(const int* __restrict__ concept,
                                             const float* __restrict__ ek,
                                             const float* __restrict__ Wf,
                                             const float* __restrict__ bf,
                                             const float* __restrict__ Wab,
                                             const float* __restrict__ bab,
                                             const float* __restrict__ Wd,
                                             const float* __restrict__ bd,
                                             float* __restrict__ out) {
    float* sWf = dynsh;                 // 8192 floats
    float* sx  = dynsh + 8192;          // 8192 floats: 64 tok x (r[64]|k[64])
    __shared__ int sc_[64];

    int tid = threadIdx.x;
    int base = blockIdx.x * 64;
    int td = tid & 15, tt = tid >> 4;   // tt 0..15

    float4* sWf4w = (float4*)sWf;
    const float4* Wf4 = (const float4*)Wf;
    for (int q = tid; q < 2048; q += 256) sWf4w[q] = Wf4[q];
    if (tid < 64) sc_[tid] = concept[base + tid];
    __syncthreads();

    float4* sx4 = (float4*)sx;
    const float4* gr4 = (const float4*)g_r;
    const float4* ek4 = (const float4*)ek;
    for (int q = tid; q < 1024; q += 256) {
        int tok = q >> 4, kk = q & 15;
        sx4[tok * 32 + kk] = gr4[(size_t)(base + tok) * 16 + kk];
        sx4[tok * 32 + 16 + kk] = ek4[(size_t)sc_[tok] * 16 + kk];
    }
    __syncthreads();

    const float4* sWf4 = (const float4*)sWf;
    float acc[4][4];
#pragma unroll
    for (int j = 0; j < 4; ++j)
#pragma unroll
        for (int dd = 0; dd < 4; ++dd) acc[j][dd] = 0.f;

#pragma unroll
    for (int kk = 0; kk < 32; ++kk) {
        float4 w0 = sWf4[(4 * kk + 0) * 16 + td];
        float4 w1 = sWf4[(4 * kk + 1) * 16 + td];
        float4 w2 = sWf4[(4 * kk + 2) * 16 + td];
        float4 w3 = sWf4[(4 * kk + 3) * 16 + td];
#pragma unroll
        for (int j = 0; j < 4; ++j) {
            float4 xv = sx4[(tt + 16 * j) * 32 + kk];
            acc[j][0] += xv.x * w0.x + xv.y * w1.x + xv.z * w2.x + xv.w * w3.x;
            acc[j][1] += xv.x * w0.y + xv.y * w1.y + xv.z * w2.y + xv.w * w3.y;
            acc[j][2] += xv.x * w0.z + xv.y * w1.z + xv.z * w2.z + xv.w * w3.z;
            acc[j][3] += xv.x * w0.w + xv.y * w1.w + xv.z * w2.w + xv.w * w3.w;
        }
    }

    float4 bfv = *(const float4*)(bf + 4 * td);
    float4 wabv = *(const float4*)(Wab + 4 * td);
    float4 wdv = *(const float4*)(Wd + 4 * td);
    float bab0 = bab[0], bd0 = bd[0];

#pragma unroll
    for (int j = 0; j < 4; ++j) {
        int tok = tt + 16 * j;
        float f0 = fast_tanh(acc[j][0] + bfv.x);
        float f1 = fast_tanh(acc[j][1] + bfv.y);
        float f2 = fast_tanh(acc[j][2] + bfv.z);
        float f3 = fast_tanh(acc[j][3] + bfv.w);
        float pa = f0 * wabv.x + f1 * wabv.y + f2 * wabv.z + f3 * wabv.w;
        float4 kd = *(const float4*)&sx[tok * 128 + 64 + 4 * td];
        float pq = kd.x * wdv.x + kd.y * wdv.y + kd.z * wdv.z + kd.w * wdv.w;
#pragma unroll
        for (int o = 8; o > 0; o >>= 1) {
            pa += __shfl_xor_sync(0xffffffffu, pa, o);
            pq += __shfl_xor_sync(0xffffffffu, pq, o);
        }
        if (td == 0) {
            float val = 3.f * fast_tanh(pa + bab0) - fast_tanh(pq + bd0);
            out[base + tok] = fast_sigmoid(val);
        }
    }
}

// ============================================================
extern "C" void kernel_launch(void* const* d_in, const int* in_sizes, int n_in,
                              void* d_out, int out_size) {
    const int*   concept = (const int*)d_in[0];
    const int*   correct = (const int*)d_in[1];
    const int*   nc      = (const int*)d_in[2];
    const float* ek      = (const float*)d_in[3];
    const float* ev      = (const float*)d_in[4];
    const float* Mk      = (const float*)d_in[5];
    const float* Mv0     = (const float*)d_in[6];
    const float* Wf      = (const float*)d_in[7];
    const float* bf      = (const float*)d_in[8];
    const float* We      = (const float*)d_in[9];
    const float* be      = (const float*)d_in[10];
    const float* Wa      = (const float*)d_in[11];
    const float* ba      = (const float*)d_in[12];
    const float* Wab     = (const float*)d_in[13];
    const float* bab     = (const float*)d_in[14];
    const float* Wd      = (const float*)d_in[15];
    const float* bd      = (const float*)d_in[16];
    float* out = (float*)d_out;

    const int EA_SMEM  = 12288 * sizeof(float);   // 48KB
    const int OUT_SMEM = 16384 * sizeof(float);   // 64KB
    cudaFuncSetAttribute(k_ea,  cudaFuncAttributeMaxDynamicSharedMemorySize, EA_SMEM);
    cudaFuncSetAttribute(k_out, cudaFuncAttributeMaxDynamicSharedMemorySize, OUT_SMEM);

    k_scores<<<500, 128>>>(concept, ek, Mk);
    k_ea<<<500, 256, EA_SMEM>>>(concept, correct, nc, ev, We, be, Wa, ba);
    k_scan<<<128, 256>>>(Mv0);
    k_out<<<500, 256, OUT_SMEM>>>(concept, ek, Wf, bf, Wab, bab, Wd, bd, out);
}

// round 7
// speedup vs baseline: 1.0497x; 1.0497x over previous
#include <cuda_runtime.h>
#include <math.h>

#define BB 64
#define TT 500
#define SS 50
#define DD 64
#define NTOK (BB*TT)

typedef unsigned long long u64;

__device__ float g_w[(size_t)NTOK*SS];
__device__ float g_e[(size_t)NTOK*DD];
__device__ float g_a[(size_t)NTOK*DD];
__device__ float g_r[(size_t)NTOK*DD];

__device__ __forceinline__ float fast_sigmoid(float x) {
    return 1.f / (1.f + __expf(-x));
}
__device__ __forceinline__ float fast_tanh(float x) {
    return fmaf(2.f, fast_sigmoid(2.f * x), -1.f);
}

// ---- packed f32x2 helpers (Blackwell FFMA2) ----
__device__ __forceinline__ u64 ffma2(u64 a, u64 b, u64 c) {
    u64 d;
    asm("fma.rn.f32x2 %0, %1, %2, %3;" : "=l"(d) : "l"(a), "l"(b), "l"(c));
    return d;
}
__device__ __forceinline__ u64 splat2(float x) {
    u64 d;
    asm("mov.b64 %0, {%1, %1};" : "=l"(d) : "r"(__float_as_uint(x)));
    return d;
}
__device__ __forceinline__ float2 unpack2(u64 v) {
    unsigned int lo, hi;
    asm("mov.b64 {%0, %1}, %2;" : "=r"(lo), "=r"(hi) : "l"(v));
    return make_float2(__uint_as_float(lo), __uint_as_float(hi));
}

// ============================================================
// k_scores: w = softmax_s(k @ Mk^T). 64 tok/block, 128 thr, grid 500.
// td = tid&15 -> s = 4*td.. ; tt = tid>>4 -> tokens tt+8j, j=0..7.
// Inner loop in packed f32x2.
// ============================================================
#define SROW 52
__global__ __launch_bounds__(128) void k_scores(const int* __restrict__ concept,
                                                const float* __restrict__ ek,
                                                const float* __restrict__ Mk) {
    __shared__ __align__(16) float sMkT[64 * SROW + 16];
    __shared__ __align__(16) float sx[64 * 64];
    __shared__ int sc_[64];

    int tid = threadIdx.x;
    int base = blockIdx.x * 64;
    int td = tid & 15, tt = tid >> 4;

    for (int q = tid; q < 64 * SROW + 16; q += 128) sMkT[q] = 0.f;
    if (tid < 64) sc_[tid] = concept[base + tid];
    __syncthreads();
    for (int q = tid; q < SS * DD; q += 128) {
        int s = q >> 6, k = q & 63;
        sMkT[k * SROW + s] = Mk[q];
    }
    __syncthreads();

    float4* sx4 = (float4*)sx;
    const float4* ek4 = (const float4*)ek;
    for (int q = tid; q < 1024; q += 128) {
        int tok = q >> 4, kk = q & 15;
        sx4[q] = ek4[(size_t)sc_[tok] * 16 + kk];
    }
    __syncthreads();

    const float4* sM4 = (const float4*)sMkT;   // row stride 13 float4
    u64 acc[8][2];
#pragma unroll
    for (int j = 0; j < 8; ++j) { acc[j][0] = 0ull; acc[j][1] = 0ull; }

#pragma unroll
    for (int kk = 0; kk < 16; ++kk) {
        ulonglong2 w0 = *(const ulonglong2*)(sM4 + (4 * kk + 0) * 13 + td);
        ulonglong2 w1 = *(const ulonglong2*)(sM4 + (4 * kk + 1) * 13 + td);
        ulonglong2 w2 = *(const ulonglong2*)(sM4 + (4 * kk + 2) * 13 + td);
        ulonglong2 w3 = *(const ulonglong2*)(sM4 + (4 * kk + 3) * 13 + td);
#pragma unroll
        for (int j = 0; j < 8; ++j) {
            float4 xv = sx4[(tt + 8 * j) * 16 + kk];
            u64 x0 = splat2(xv.x), x1 = splat2(xv.y), x2 = splat2(xv.z), x3 = splat2(xv.w);
            acc[j][0] = ffma2(x0, w0.x, acc[j][0]);
            acc[j][1] = ffma2(x0, w0.y, acc[j][1]);
            acc[j][0] = ffma2(x1, w1.x, acc[j][0]);
            acc[j][1] = ffma2(x1, w1.y, acc[j][1]);
            acc[j][0] = ffma2(x2, w2.x, acc[j][0]);
            acc[j][1] = ffma2(x2, w2.y, acc[j][1]);
            acc[j][0] = ffma2(x3, w3.x, acc[j][0]);
            acc[j][1] = ffma2(x3, w3.y, acc[j][1]);
        }
    }

#pragma unroll
    for (int j = 0; j < 8; ++j) {
        float2 a01 = unpack2(acc[j][0]);
        float2 a23 = unpack2(acc[j][1]);
        float s0 = a01.x, s1 = a01.y, s2 = a23.x, s3 = a23.y;
        float e0 = (4 * td + 0) < SS ? __expf(s0) : 0.f;
        float e1 = (4 * td + 1) < SS ? __expf(s1) : 0.f;
        float e2 = (4 * td + 2) < SS ? __expf(s2) : 0.f;
        float e3 = (4 * td + 3) < SS ? __expf(s3) : 0.f;
        float p = e0 + e1 + e2 + e3;
        p += __shfl_xor_sync(0xffffffffu, p, 1);
        p += __shfl_xor_sync(0xffffffffu, p, 2);
        p += __shfl_xor_sync(0xffffffffu, p, 4);
        p += __shfl_xor_sync(0xffffffffu, p, 8);
        float inv = 1.f / p;
        int tok = base + tt + 8 * j;
        float* gwp = g_w + (size_t)tok * SS + 4 * td;
        if (td < 12) {
            *(float2*)gwp       = make_float2(e0 * inv, e1 * inv);
            *(float2*)(gwp + 2) = make_float2(e2 * inv, e3 * inv);
        } else if (td == 12) {
            *(float2*)gwp       = make_float2(e0 * inv, e1 * inv);
        }
    }
}

// ============================================================
// k_ea: e = sigmoid(v@We+be), a = tanh(v@Wa+ba). 64 tok/block, 256 thr.
// Dynamic smem 48KB. Packed f32x2 inner loop; each splat feeds 4 FFMA2.
// ============================================================
extern __shared__ float dynsh[];
__global__ __launch_bounds__(256) void k_ea(const int* __restrict__ concept,
                                            const int* __restrict__ correct,
                                            const int* __restrict__ nc_ptr,
                                            const float* __restrict__ ev,
                                            const float* __restrict__ We,
                                            const float* __restrict__ be,
                                            const float* __restrict__ Wa,
                                            const float* __restrict__ ba) {
    float* sWe = dynsh;
    float* sWa = dynsh + 4096;
    float* sx  = dynsh + 8192;
    __shared__ int sidx[64];

    int tid = threadIdx.x;
    int base = blockIdx.x * 64;
    int td = tid & 15, tt = tid >> 4;
    int nc = *nc_ptr;

    float4* sWe4w = (float4*)sWe;
    float4* sWa4w = (float4*)sWa;
    const float4* We4 = (const float4*)We;
    const float4* Wa4 = (const float4*)Wa;
    for (int q = tid; q < 1024; q += 256) {
        sWe4w[q] = We4[q];
        sWa4w[q] = Wa4[q];
    }
    if (tid < 64) sidx[tid] = concept[base + tid] + nc * correct[base + tid];
    __syncthreads();

    float4* sx4 = (float4*)sx;
    const float4* ev4 = (const float4*)ev;
    for (int q = tid; q < 1024; q += 256) {
        int tok = q >> 4, kk = q & 15;
        sx4[q] = ev4[(size_t)sidx[tok] * 16 + kk];
    }
    __syncthreads();

    const float4* sWe4 = (const float4*)sWe;
    const float4* sWa4 = (const float4*)sWa;
    u64 ae[4][2], aa[4][2];
#pragma unroll
    for (int j = 0; j < 4; ++j) {
        ae[j][0] = ae[j][1] = 0ull;
        aa[j][0] = aa[j][1] = 0ull;
    }

#pragma unroll
    for (int kk = 0; kk < 16; ++kk) {
        ulonglong2 e0 = *(const ulonglong2*)(sWe4 + (4 * kk + 0) * 16 + td);
        ulonglong2 e1 = *(const ulonglong2*)(sWe4 + (4 * kk + 1) * 16 + td);
        ulonglong2 e2 = *(const ulonglong2*)(sWe4 + (4 * kk + 2) * 16 + td);
        ulonglong2 e3 = *(const ulonglong2*)(sWe4 + (4 * kk + 3) * 16 + td);
        ulonglong2 a0 = *(const ulonglong2*)(sWa4 + (4 * kk + 0) * 16 + td);
        ulonglong2 a1 = *(const ulonglong2*)(sWa4 + (4 * kk + 1) * 16 + td);
        ulonglong2 a2 = *(const ulonglong2*)(sWa4 + (4 * kk + 2) * 16 + td);
        ulonglong2 a3 = *(const ulonglong2*)(sWa4 + (4 * kk + 3) * 16 + td);
#pragma unroll
        for (int j = 0; j < 4; ++j) {
            float4 xv = sx4[(tt + 16 * j) * 16 + kk];
            u64 x0 = splat2(xv.x), x1 = splat2(xv.y), x2 = splat2(xv.z), x3 = splat2(xv.w);
            ae[j][0] = ffma2(x0, e0.x, ae[j][0]);
            ae[j][1] = ffma2(x0, e0.y, ae[j][1]);
            aa[j][0] = ffma2(x0, a0.x, aa[j][0]);
            aa[j][1] = ffma2(x0, a0.y, aa[j][1]);
            ae[j][0] = ffma2(x1, e1.x, ae[j][0]);
            ae[j][1] = ffma2(x1, e1.y, ae[j][1]);
            aa[j][0] = ffma2(x1, a1.x, aa[j][0]);
            aa[j][1] = ffma2(x1, a1.y, aa[j][1]);
            ae[j][0] = ffma2(x2, e2.x, ae[j][0]);
            ae[j][1] = ffma2(x2, e2.y, ae[j][1]);
            aa[j][0] = ffma2(x2, a2.x, aa[j][0]);
            aa[j][1] = ffma2(x2, a2.y, aa[j][1]);
            ae[j][0] = ffma2(x3, e3.x, ae[j][0]);
            ae[j][1] = ffma2(x3, e3.y, ae[j][1]);
            aa[j][0] = ffma2(x3, a3.x, aa[j][0]);
            aa[j][1] = ffma2(x3, a3.y, aa[j][1]);
        }
    }

    float4 bev = *(const float4*)(be + 4 * td);
    float4 bav = *(const float4*)(ba + 4 * td);
#pragma unroll
    for (int j = 0; j < 4; ++j) {
        size_t tok = (size_t)(base + tt + 16 * j);
        float2 ae01 = unpack2(ae[j][0]);
        float2 ae23 = unpack2(ae[j][1]);
        float2 aa01 = unpack2(aa[j][0]);
        float2 aa23 = unpack2(aa[j][1]);
        float4 eo, ao;
        eo.x = fast_sigmoid(ae01.x + bev.x);
        eo.y = fast_sigmoid(ae01.y + bev.y);
        eo.z = fast_sigmoid(ae23.x + bev.z);
        eo.w = fast_sigmoid(ae23.y + bev.w);
        ao.x = fast_tanh(aa01.x + bav.x);
        ao.y = fast_tanh(aa01.y + bav.y);
        ao.z = fast_tanh(aa23.x + bav.z);
        ao.w = fast_tanh(aa23.y + bav.w);
        *(float4*)(g_e + tok * DD + 4 * td) = eo;
        *(float4*)(g_a + tok * DD + 4 * td) = ao;
    }
}

// ============================================================
// k_scan: 256 blocks = (b, d-quarter), 128 thr. (R5 best-measured version)
// ============================================================
#define CH 10
__global__ __launch_bounds__(128) void k_scan(const float* __restrict__ Mv0) {
    int b = blockIdx.x >> 2, dq = blockIdx.x & 3;
    int tid = threadIdx.x;
    int dl = tid >> 3, h = tid & 7;
    int d = dq * 16 + dl;
    int sbase = h * 7;

    __shared__ __align__(16) float sw[2][CH][56];
    __shared__ __align__(16) float se[2][CH][16];
    __shared__ __align__(16) float sa[2][CH][16];
    __shared__ __align__(16) float srb[CH][16];

    for (int q = tid; q < 2 * CH * 6; q += 128) {
        int bf = q / (CH * 6), rem = q % (CH * 6), t = rem / 6, p = rem % 6;
        sw[bf][t][50 + p] = 0.f;
    }

    float mv[7];
#pragma unroll
    for (int i = 0; i < 7; i++) {
        int s = sbase + i;
        mv[i] = (s < SS) ? Mv0[s * DD + d] : 0.f;
    }

    const float* gw = g_w + (size_t)b * TT * SS;
    const float* ge = g_e + (size_t)b * TT * DD + dq * 16;
    const float* ga = g_a + (size_t)b * TT * DD + dq * 16;
    float* gr = g_r + (size_t)b * TT * DD + dq * 16;

    float2 wreg[2];
    float4 eareg;

#pragma unroll
    for (int n = 0; n < 2; n++) {
        int q = tid + 128 * n;
        if (q < CH * 25) { int t = q / 25, p = q % 25; wreg[n] = *(const float2*)(gw + (size_t)t * SS + 2 * p); }
    }
    if (tid < 40)      { int t = tid / 4, p = tid % 4; eareg = *(const float4*)(ge + (size_t)t * DD + 4 * p); }
    else if (tid < 80) { int q = tid - 40; int t = q / 4, p = q % 4; eareg = *(const float4*)(ga + (size_t)t * DD + 4 * p); }

#pragma unroll
    for (int n = 0; n < 2; n++) {
        int q = tid + 128 * n;
        if (q < CH * 25) { int t = q / 25, p = q % 25; *(float2*)&sw[0][t][2 * p] = wreg[n]; }
    }
    if (tid < 40)      { int t = tid / 4, p = tid % 4; *(float4*)&se[0][t][4 * p] = eareg; }
    else if (tid < 80) { int q = tid - 40; int t = q / 4, p = q % 4; *(float4*)&sa[0][t][4 * p] = eareg; }
    __syncthreads();

    for (int c = 0; c < TT / CH; ++c) {
        int cur = c & 1;
        if (c < TT / CH - 1) {
            int t0 = (c + 1) * CH;
#pragma unroll
            for (int n = 0; n < 2; n++) {
                int q = tid + 128 * n;
                if (q < CH * 25) { int t = q / 25, p = q % 25; wreg[n] = *(const float2*)(gw + (size_t)(t0 + t) * SS + 2 * p); }
            }
            if (tid < 40)      { int t = tid / 4, p = tid % 4; eareg = *(const float4*)(ge + (size_t)(t0 + t) * DD + 4 * p); }
            else if (tid < 80) { int q = tid - 40; int t = q / 4, p = q % 4; eareg = *(const float4*)(ga + (size_t)(t0 + t) * DD + 4 * p); }
        }

#pragma unroll
        for (int tl = 0; tl < CH; ++tl) {
            float e_d = se[cur][tl][dl], a_d = sa[cur][tl][dl];
            float r = 0.f;
#pragma unroll
            for (int i = 0; i < 7; i++) {
                float ws = sw[cur][tl][sbase + i];
                r += ws * mv[i];
                mv[i] = fmaf(ws, fmaf(-mv[i], e_d, a_d), mv[i]);
            }
            r += __shfl_xor_sync(0xffffffffu, r, 1);
            r += __shfl_xor_sync(0xffffffffu, r, 2);
            r += __shfl_xor_sync(0xffffffffu, r, 4);
            if (h == 0) srb[tl][dl] = r;
        }
        __syncthreads();

        {
            int t0 = c * CH;
            if (tid < 40) {
                int t = tid / 4, p = tid % 4;
                *(float4*)(gr + (size_t)(t0 + t) * DD + 4 * p) = *(const float4*)&srb[t][4 * p];
            }
        }
        if (c < TT / CH - 1) {
            int nb = cur ^ 1;
#pragma unroll
            for (int n = 0; n < 2; n++) {
                int q = tid + 128 * n;
                if (q < CH * 25) { int t = q / 25, p = q % 25; *(float2*)&sw[nb][t][2 * p] = wreg[n]; }
            }
            if (tid < 40)      { int t = tid / 4, p = tid % 4; *(float4*)&se[nb][t][4 * p] = eareg; }
            else if (tid < 80) { int q = tid - 40; int t = q / 4, p = q % 4; *(float4*)&sa[nb][t][4 * p] = eareg; }
        }
        __syncthreads();
    }
}

// ============================================================
// k_out: 64 tok/block, 256 thr, grid 500, 64KB smem. Packed f32x2 inner.
// ============================================================
__global__ __launch_bounds__(256) void k_out(const int* __restrict__ concept,
                                             const float* __restrict__ ek,
                                             const float* __restrict__ Wf,
                                             const float* __restrict__ bf,
                                             const float* __restrict__ Wab,
                                             const float* __restrict__ bab,
                                             const float* __restrict__ Wd,
                                             const float* __restrict__ bd,
                                             float* __restrict__ out) {
    float* sWf = dynsh;                 // 8192 floats
    float* sx  = dynsh + 8192;          // 8192 floats: 64 tok x (r[64]|k[64])
    __shared__ int sc_[64];

    int tid = threadIdx.x;
    int base = blockIdx.x * 64;
    int td = tid & 15, tt = tid >> 4;   // tt 0..15

    float4* sWf4w = (float4*)sWf;
    const float4* Wf4 = (const float4*)Wf;
    for (int q = tid; q < 2048; q += 256) sWf4w[q] = Wf4[q];
    if (tid < 64) sc_[tid] = concept[base + tid];
    __syncthreads();

    float4* sx4 = (float4*)sx;
    const float4* gr4 = (const float4*)g_r;
    const float4* ek4 = (const float4*)ek;
    for (int q = tid; q < 1024; q += 256) {
        int tok = q >> 4, kk = q & 15;
        sx4[tok * 32 + kk] = gr4[(size_t)(base + tok) * 16 + kk];
        sx4[tok * 32 + 16 + kk] = ek4[(size_t)sc_[tok] * 16 + kk];
    }
    __syncthreads();

    const float4* sWf4 = (const float4*)sWf;
    u64 acc[4][2];
#pragma unroll
    for (int j = 0; j < 4; ++j) { acc[j][0] = 0ull; acc[j][1] = 0ull; }

#pragma unroll
    for (int kk = 0; kk < 32; ++kk) {
        ulonglong2 w0 = *(const ulonglong2*)(sWf4 + (4 * kk + 0) * 16 + td);
        ulonglong2 w1 = *(const ulonglong2*)(sWf4 + (4 * kk + 1) * 16 + td);
        ulonglong2 w2 = *(const ulonglong2*)(sWf4 + (4 * kk + 2) * 16 + td);
        ulonglong2 w3 = *(const ulonglong2*)(sWf4 + (4 * kk + 3) * 16 + td);
#pragma unroll
        for (int j = 0; j < 4; ++j) {
            float4 xv = sx4[(tt + 16 * j) * 32 + kk];
            u64 x0 = splat2(xv.x), x1 = splat2(xv.y), x2 = splat2(xv.z), x3 = splat2(xv.w);
            acc[j][0] = ffma2(x0, w0.x, acc[j][0]);
            acc[j][1] = ffma2(x0, w0.y, acc[j][1]);
            acc[j][0] = ffma2(x1, w1.x, acc[j][0]);
            acc[j][1] = ffma2(x1, w1.y, acc[j][1]);
            acc[j][0] = ffma2(x2, w2.x, acc[j][0]);
            acc[j][1] = ffma2(x2, w2.y, acc[j][1]);
            acc[j][0] = ffma2(x3, w3.x, acc[j][0]);
            acc[j][1] = ffma2(x3, w3.y, acc[j][1]);
        }
    }

    float4 bfv = *(const float4*)(bf + 4 * td);
    float4 wabv = *(const float4*)(Wab + 4 * td);
    float4 wdv = *(const float4*)(Wd + 4 * td);
    float bab0 = bab[0], bd0 = bd[0];

#pragma unroll
    for (int j = 0; j < 4; ++j) {
        int tok = tt + 16 * j;
        float2 a01 = unpack2(acc[j][0]);
        float2 a23 = unpack2(acc[j][1]);
        float f0 = fast_tanh(a01.x + bfv.x);
        float f1 = fast_tanh(a01.y + bfv.y);
        float f2 = fast_tanh(a23.x + bfv.z);
        float f3 = fast_tanh(a23.y + bfv.w);
        float pa = f0 * wabv.x + f1 * wabv.y + f2 * wabv.z + f3 * wabv.w;
        float4 kd = *(const float4*)&sx[tok * 128 + 64 + 4 * td];
        float pq = kd.x * wdv.x + kd.y * wdv.y + kd.z * wdv.z + kd.w * wdv.w;
#pragma unroll
        for (int o = 8; o > 0; o >>= 1) {
            pa += __shfl_xor_sync(0xffffffffu, pa, o);
            pq += __shfl_xor_sync(0xffffffffu, pq, o);
        }
        if (td == 0) {
            float val = 3.f * fast_tanh(pa + bab0) - fast_tanh(pq + bd0);
            out[base + tok] = fast_sigmoid(val);
        }
    }
}

// ============================================================
extern "C" void kernel_launch(void* const* d_in, const int* in_sizes, int n_in,
                              void* d_out, int out_size) {
    const int*   concept = (const int*)d_in[0];
    const int*   correct = (const int*)d_in[1];
    const int*   nc      = (const int*)d_in[2];
    const float* ek      = (const float*)d_in[3];
    const float* ev      = (const float*)d_in[4];
    const float* Mk      = (const float*)d_in[5];
    const float* Mv0     = (const float*)d_in[6];
    const float* Wf      = (const float*)d_in[7];
    const float* bf      = (const float*)d_in[8];
    const float* We      = (const float*)d_in[9];
    const float* be      = (const float*)d_in[10];
    const float* Wa      = (const float*)d_in[11];
    const float* ba      = (const float*)d_in[12];
    const float* Wab     = (const float*)d_in[13];
    const float* bab     = (const float*)d_in[14];
    const float* Wd      = (const float*)d_in[15];
    const float* bd      = (const float*)d_in[16];
    float* out = (float*)d_out;

    const int EA_SMEM  = 12288 * sizeof(float);   // 48KB
    const int OUT_SMEM = 16384 * sizeof(float);   // 64KB
    cudaFuncSetAttribute(k_ea,  cudaFuncAttributeMaxDynamicSharedMemorySize, EA_SMEM);
    cudaFuncSetAttribute(k_out, cudaFuncAttributeMaxDynamicSharedMemorySize, OUT_SMEM);

    k_scores<<<500, 128>>>(concept, ek, Mk);
    k_ea<<<500, 256, EA_SMEM>>>(concept, correct, nc, ev, We, be, Wa, ba);
    k_scan<<<256, 128>>>(Mv0);
    k_out<<<500, 256, OUT_SMEM>>>(concept, ek, Wf, bf, Wab, bab, Wd, bd, out);
}